// round 15
// baseline (speedup 1.0000x reference)
#include <cuda_runtime.h>
#include <cuda_bf16.h>
#include <cuda_fp16.h>
#include <cstdint>

// Problem constants (fixed by dataset)
#define NMAX   20000
#define EMAX   320000
#define DIN    512
#define DH     256
#define NGR    128
#define NCSR   128                     // CSR-builder blocks inside hybrid kernel
#define CSR_THREADS (NCSR * 128)

// ---------------- scratch (static device globals; no runtime alloc) ----------
__device__ int   g_deg[NMAX];
__device__ int   g_rowstart[NMAX + 1];
__device__ int   g_cursor[NMAX];
__device__ int   g_csr[EMAX];
__device__ float g_dinv[NMAX];
__device__ __align__(16) __nv_bfloat16 g_yb[(size_t)NMAX * DH];   // bf16 gemm out (gather src)
__device__ __align__(16) __half g_h[(size_t)NMAX * DH];           // layer-1 hidden (fp16)
__device__ __align__(16) uint32_t g_w1p[(DIN / 2) * DH];          // W1 packed half2 pairs
__device__ __align__(16) uint32_t g_w2p[(DH / 2) * DH];           // W2 packed half2 pairs
__device__ float g_gsum[NGR];
__device__ int   g_cnt[NGR];
__device__ int   g_blocksum[NCSR];
__device__ int   g_done;               // agg2 block completion counter
__device__ volatile unsigned g_bar[4];

// ---------------- helpers -----------------------------------------------------
__device__ __forceinline__ uint32_t packh2(float a, float b) {
    __half2 h = __float22half2_rn(make_float2(a, b));
    return *reinterpret_cast<uint32_t*>(&h);
}

__device__ __forceinline__ void cpa16(uint32_t dst_smem, const void* src, int srcsize) {
    asm volatile("cp.async.cg.shared.global [%0], [%1], 16, %2;\n"
                 :: "r"(dst_smem), "l"(src), "r"(srcsize));
}
#define CP_COMMIT() asm volatile("cp.async.commit_group;\n" ::: "memory")
#define CP_WAIT0()  asm volatile("cp.async.wait_group 0;\n" ::: "memory")

// ---------------- prep: reset counters + pack W1/W2 into fp16 pair layout -----
__global__ void prep_kernel(const float* __restrict__ W1, const float* __restrict__ W2) {
    int gid = blockIdx.x * blockDim.x + threadIdx.x;
    int nthr = gridDim.x * blockDim.x;
    if (gid < 4) g_bar[gid] = 0u;
    if (gid == 0) g_done = 0;
    const int t1 = (DIN / 2) * DH;
    for (int i = gid; i < t1; i += nthr) {
        int kp = i / DH, n = i % DH;
        g_w1p[i] = packh2(W1[(2 * kp) * DH + n], W1[(2 * kp + 1) * DH + n]);
    }
    const int t2 = (DH / 2) * DH;
    for (int i = gid; i < t2; i += nthr) {
        int kp = i / DH, n = i % DH;
        g_w2p[i] = packh2(W2[(2 * kp) * DH + n], W2[(2 * kp + 1) * DH + n]);
    }
}

// ---------------- spin barrier among the NCSR builder blocks ------------------
__device__ __forceinline__ void csr_barrier(int id) {
    __syncthreads();
    if (threadIdx.x == 0) {
        __threadfence();
        atomicAdd((unsigned*)(g_bar + id), 1u);
        while (g_bar[id] < (unsigned)NCSR) __nanosleep(128);
        __threadfence();
    }
    __syncthreads();
}

// ---------------- CSR build (blocks [0,NCSR) of hybrid kernel; 128 threads) ---
__device__ void csr_build(const int* __restrict__ ei, const int* __restrict__ batch,
                          int n, int e) {
    int tid  = threadIdx.x;
    int gtid = blockIdx.x * 128 + tid;

    __shared__ int sm[4];
    __shared__ int s_carry;

    for (int i = gtid; i < n; i += CSR_THREADS) g_deg[i] = 0;
    if (gtid < NGR) { g_gsum[gtid] = 0.0f; g_cnt[gtid] = 0; }
    if (gtid == 0)  g_rowstart[n] = e;
    csr_barrier(0);

    for (int i = gtid; i < e; i += CSR_THREADS) atomicAdd(&g_deg[ei[e + i]], 1);
    for (int i = gtid; i < n; i += CSR_THREADS) atomicAdd(&g_cnt[batch[i]], 1);
    csr_barrier(1);

    const int chunk = (n + NCSR - 1) / NCSR;
    int base = blockIdx.x * chunk;
    int lim  = n - base; if (lim > chunk) lim = chunk; if (lim < 0) lim = 0;

    int lane = tid & 31, wid = tid >> 5;

    int psum = 0;
    for (int i = tid; i < lim; i += 128) psum += __ldcg(&g_deg[base + i]);
    #pragma unroll
    for (int off = 16; off; off >>= 1) psum += __shfl_xor_sync(0xffffffffu, psum, off);
    if (lane == 0) sm[wid] = psum;
    __syncthreads();
    if (tid == 0) g_blocksum[blockIdx.x] = sm[0] + sm[1] + sm[2] + sm[3];
    csr_barrier(2);

    {
        int val = (tid < blockIdx.x) ? __ldcg(&g_blocksum[tid]) : 0;
        #pragma unroll
        for (int off = 16; off; off >>= 1) val += __shfl_xor_sync(0xffffffffu, val, off);
        if (lane == 0) sm[wid] = val;
        __syncthreads();
        if (tid == 0) s_carry = sm[0] + sm[1] + sm[2] + sm[3];
        __syncthreads();
    }
    int run = s_carry;
    __syncthreads();

    for (int o = 0; o < lim; o += 128) {
        int i = base + o + tid;
        int v = (o + tid < lim) ? __ldcg(&g_deg[i]) : 0;
        int x = v;
        #pragma unroll
        for (int off = 1; off < 32; off <<= 1) {
            int t = __shfl_up_sync(0xffffffffu, x, off);
            if (lane >= off) x += t;
        }
        if (lane == 31) sm[wid] = x;
        __syncthreads();
        if (wid == 0 && lane < 4) {
            int s = sm[lane];
            #pragma unroll
            for (int off = 1; off < 4; off <<= 1) {
                int t = __shfl_up_sync(0xfu, s, off);
                if (lane >= off) s += t;
            }
            sm[lane] = s;
        }
        __syncthreads();
        int woff = wid ? sm[wid - 1] : 0;
        if (o + tid < lim) {
            int excl = run + x + woff - v;
            g_rowstart[i] = excl;
            g_cursor[i]   = excl;
            g_dinv[i]     = rsqrtf((float)(v + 1));
        }
        run += sm[3];
        __syncthreads();
    }
    csr_barrier(3);

    for (int i = gtid; i < e; i += CSR_THREADS) {
        int s = ei[i];
        int d = ei[e + i];
        int p = atomicAdd(&g_cursor[d], 1);
        g_csr[p] = s;
    }
}

// ---------------- fp16 tensor-core GEMM (m16n8k16, fp32 accum) ----------------
__device__ __forceinline__ void mma_f16(float* c, const uint32_t* a, const uint32_t* b) {
    asm volatile(
        "mma.sync.aligned.m16n8k16.row.col.f32.f16.f16.f32 "
        "{%0,%1,%2,%3}, {%4,%5,%6,%7}, {%8,%9}, {%0,%1,%2,%3};\n"
        : "+f"(c[0]), "+f"(c[1]), "+f"(c[2]), "+f"(c[3])
        : "r"(a[0]), "r"(a[1]), "r"(a[2]), "r"(a[3]),
          "r"(b[0]), "r"(b[1]));
}

#define BM 128
#define BN 64
#define KPT 16      // k-pairs per tile (= 32 k-values)
#define ASPAD 20
#define BSPAD 72

template <int AF16>
__device__ __forceinline__ void gemm_core(
    const float* __restrict__ Af, const uint32_t* __restrict__ Ah,
    const uint32_t* __restrict__ Bp,
    const float* __restrict__ scale, __nv_bfloat16* __restrict__ Yb,
    int M, int K, int bid,
    uint32_t (*As)[ASPAD], uint32_t (*Bs)[BSPAD]) {

    int tid  = threadIdx.x;
    int lane = tid & 31, warp = tid >> 5;
    int wm = warp >> 1, wn = warp & 1;
    int gid = lane >> 2, tig = lane & 3;
    int m0 = (bid >> 2) * BM;
    int n0 = (bid & 3) * BN;
    const int KPr = K >> 1;

    uint32_t as_base = (uint32_t)__cvta_generic_to_shared(&As[0][0]);
    uint32_t bs_base = (uint32_t)__cvta_generic_to_shared(&Bs[0][0]);

    float c[4][4][4] = {};
    float4 pa[8];

    auto loadB = [&](int kt, int s) {
        const uint32_t* src = Bp + (size_t)(kt * KPT) * DH + n0;
        #pragma unroll
        for (int t = 0; t < 2; ++t) {
            int cidx = tid + t * 128;
            int kp = cidx >> 4, cc = (cidx & 15) << 2;
            cpa16(bs_base + (((s * KPT + kp) * BSPAD) + cc) * 4, src + kp * DH + cc, 16);
        }
    };
    auto loadA16 = [&](int kt, int s) {
        #pragma unroll
        for (int t = 0; t < 4; ++t) {
            int cidx = tid + t * 128;
            int r = cidx >> 2, cc = (cidx & 3) << 2;
            int gr = m0 + r;
            int sz = (gr < M) ? 16 : 0;
            const uint32_t* src = Ah + (size_t)(gr < M ? gr : 0) * KPr + kt * KPT + cc;
            cpa16(as_base + (((s * BM + r) * ASPAD) + cc) * 4, src, sz);
        }
    };
    auto ldAreg = [&](int kt) {
        #pragma unroll
        for (int t = 0; t < 8; ++t) {
            int f4 = tid + t * 128;
            int r = f4 >> 3, cc = (f4 & 7) << 2;
            int gr = m0 + r;
            pa[t] = (gr < M) ? *(const float4*)(Af + (size_t)gr * K + kt * 32 + cc)
                             : make_float4(0.f, 0.f, 0.f, 0.f);
        }
    };
    auto stA = [&](int s) {
        #pragma unroll
        for (int t = 0; t < 8; ++t) {
            int f4 = tid + t * 128;
            int r = f4 >> 3, cc = (f4 & 7) << 2;
            uint2 v = make_uint2(packh2(pa[t].x, pa[t].y), packh2(pa[t].z, pa[t].w));
            *(uint2*)&As[s * BM + r][cc >> 1] = v;
        }
    };
    auto compute = [&](int s) {
        #pragma unroll
        for (int ks = 0; ks < 2; ++ks) {
            int kk2 = ks * 8;
            uint32_t a[4][4], b[4][2];
            #pragma unroll
            for (int i = 0; i < 4; ++i) {
                int mrow = s * BM + wm * 64 + i * 16;
                a[i][0] = As[mrow + gid][kk2 + tig];
                a[i][1] = As[mrow + gid + 8][kk2 + tig];
                a[i][2] = As[mrow + gid][kk2 + tig + 4];
                a[i][3] = As[mrow + gid + 8][kk2 + tig + 4];
            }
            #pragma unroll
            for (int j = 0; j < 4; ++j) {
                int ncol = wn * 32 + j * 8 + gid;
                b[j][0] = Bs[s * KPT + kk2 + tig][ncol];
                b[j][1] = Bs[s * KPT + kk2 + tig + 4][ncol];
            }
            #pragma unroll
            for (int i = 0; i < 4; ++i)
                #pragma unroll
                for (int j = 0; j < 4; ++j)
                    mma_f16(c[i][j], a[i], b[j]);
        }
    };

    int KT = K / 32;
    loadB(0, 0);
    if (AF16) loadA16(0, 0); else ldAreg(0);
    CP_COMMIT();
    if (!AF16) stA(0);
    CP_WAIT0();
    __syncthreads();

    for (int kt = 0; kt < KT; ++kt) {
        int s = kt & 1;
        if (kt + 1 < KT) {
            loadB(kt + 1, s ^ 1);
            if (AF16) loadA16(kt + 1, s ^ 1); else ldAreg(kt + 1);
            CP_COMMIT();
        }
        compute(s);
        if (!AF16 && kt + 1 < KT) stA(s ^ 1);
        if (kt + 1 < KT) { CP_WAIT0(); __syncthreads(); }
    }

    #pragma unroll
    for (int i = 0; i < 4; ++i) {
        int r0 = m0 + wm * 64 + i * 16 + gid;
        int r1 = r0 + 8;
        float s0 = 1.f, s1 = 1.f;
        if (scale) {
            s0 = (r0 < M) ? scale[r0] : 0.f;
            s1 = (r1 < M) ? scale[r1] : 0.f;
        }
        #pragma unroll
        for (int j = 0; j < 4; ++j) {
            int cb = n0 + wn * 32 + j * 8 + tig * 2;
            if (r0 < M) {
                __nv_bfloat162 v = __float22bfloat162_rn(
                    make_float2(s0 * c[i][j][0], s0 * c[i][j][1]));
                *(__nv_bfloat162*)(Yb + (size_t)r0 * DH + cb) = v;
            }
            if (r1 < M) {
                __nv_bfloat162 v = __float22bfloat162_rn(
                    make_float2(s1 * c[i][j][2], s1 * c[i][j][3]));
                *(__nv_bfloat162*)(Yb + (size_t)r1 * DH + cb) = v;
            }
        }
    }
}

// hybrid: blocks [0,NCSR) build CSR; the rest compute Yb = bf16(X @ W1) (unscaled)
__global__ __launch_bounds__(128, 2)
void hybrid_kernel(const float* __restrict__ x,
                   __nv_bfloat16* __restrict__ yb, int n,
                   const int* __restrict__ ei, const int* __restrict__ batch, int e) {
    __shared__ __align__(16) uint32_t As[2 * BM][ASPAD];
    __shared__ __align__(16) uint32_t Bs[2 * KPT][BSPAD];
    if (blockIdx.x < NCSR) { csr_build(ei, batch, n, e); return; }
    gemm_core<0>(x, nullptr, g_w1p, nullptr, yb, n, DIN, blockIdx.x - NCSR, As, Bs);
}

// gemm2: yb = bf16( dinv[m] * (h @ W2) ), all-fp16 operands, pure cp.async
__global__ __launch_bounds__(128, 3)
void gemm2_kernel(__nv_bfloat16* __restrict__ Yb, int M) {
    __shared__ __align__(16) uint32_t As[2 * BM][ASPAD];
    __shared__ __align__(16) uint32_t Bs[2 * KPT][BSPAD];
    gemm_core<1>(nullptr, (const uint32_t*)g_h, g_w2p, g_dinv, Yb, M, DH, blockIdx.x, As, Bs);
}

// ---------------- gather helper ------------------------------------------------
__device__ __forceinline__ void acc8(float* acc, uint4 v, float dv) {
    const __nv_bfloat162* b = reinterpret_cast<const __nv_bfloat162*>(&v);
    #pragma unroll
    for (int q = 0; q < 4; ++q) {
        float2 f = __bfloat1622float2(b[q]);
        acc[2 * q]     = fmaf(dv, f.x, acc[2 * q]);
        acc[2 * q + 1] = fmaf(dv, f.y, acc[2 * q + 1]);
    }
}

// edge-range partial gather (with per-src dinv if DV=1)
template <int DV>
__device__ __forceinline__ void gather_range(
    float* acc, const __nv_bfloat16* __restrict__ yb, int lo, int hi, int lane) {
    int e = lo;
    for (; e + 4 <= hi; e += 4) {
        int s0 = g_csr[e], s1 = g_csr[e + 1], s2 = g_csr[e + 2], s3 = g_csr[e + 3];
        float d0 = DV ? g_dinv[s0] : 1.f, d1 = DV ? g_dinv[s1] : 1.f;
        float d2 = DV ? g_dinv[s2] : 1.f, d3 = DV ? g_dinv[s3] : 1.f;
        uint4 v0 = ((const uint4*)(yb + (size_t)s0 * DH))[lane];
        uint4 v1 = ((const uint4*)(yb + (size_t)s1 * DH))[lane];
        uint4 v2 = ((const uint4*)(yb + (size_t)s2 * DH))[lane];
        uint4 v3 = ((const uint4*)(yb + (size_t)s3 * DH))[lane];
        acc8(acc, v0, d0); acc8(acc, v1, d1); acc8(acc, v2, d2); acc8(acc, v3, d3);
    }
    for (; e < hi; ++e) {
        int s = g_csr[e];
        uint4 v = ((const uint4*)(yb + (size_t)s * DH))[lane];
        acc8(acc, v, DV ? g_dinv[s] : 1.f);
    }
}

// layer 1: 2 warps per node (split edge range, smem combine); output fp16 h.
__global__ __launch_bounds__(256)
void aggregate1_kernel(const __nv_bfloat16* __restrict__ yb,
                       const float* __restrict__ bias,
                       __half* __restrict__ out, int n) {
    __shared__ float sbuf[4][32][9];
    int sub  = threadIdx.x >> 6;          // node slot 0..3
    int half = (threadIdx.x >> 5) & 1;    // warp within pair
    int lane = threadIdx.x & 31;
    int gw = blockIdx.x * 4 + sub;

    float acc[8] = {};
    int e0 = 0, e1 = 0;
    if (gw < n) { e0 = g_rowstart[gw]; e1 = g_rowstart[gw + 1]; }
    int mid = e0 + ((e1 - e0) >> 1);
    int lo = half ? mid : e0;
    int hi = half ? e1 : mid;
    gather_range<1>(acc, yb, lo, hi, lane);
    if (half && gw < n) {   // self loop on warp 1
        uint4 v = ((const uint4*)(yb + (size_t)gw * DH))[lane];
        acc8(acc, v, g_dinv[gw]);
    }
    if (half) {
        #pragma unroll
        for (int q = 0; q < 8; ++q) sbuf[sub][lane][q] = acc[q];
    }
    __syncthreads();
    if (!half && gw < n) {
        #pragma unroll
        for (int q = 0; q < 8; ++q) acc[q] += sbuf[sub][lane][q];
        float dvn = g_dinv[gw];
        float4 b0 = ((const float4*)bias)[2 * lane];
        float4 b1 = ((const float4*)bias)[2 * lane + 1];
        float r[8];
        r[0] = fmaxf(dvn * acc[0] + b0.x, 0.f); r[1] = fmaxf(dvn * acc[1] + b0.y, 0.f);
        r[2] = fmaxf(dvn * acc[2] + b0.z, 0.f); r[3] = fmaxf(dvn * acc[3] + b0.w, 0.f);
        r[4] = fmaxf(dvn * acc[4] + b1.x, 0.f); r[5] = fmaxf(dvn * acc[5] + b1.y, 0.f);
        r[6] = fmaxf(dvn * acc[6] + b1.z, 0.f); r[7] = fmaxf(dvn * acc[7] + b1.w, 0.f);
        uint4 st;
        uint32_t* sp = reinterpret_cast<uint32_t*>(&st);
        sp[0] = packh2(r[0], r[1]); sp[1] = packh2(r[2], r[3]);
        sp[2] = packh2(r[4], r[5]); sp[3] = packh2(r[6], r[7]);
        ((uint4*)(out + (size_t)gw * DH))[lane] = st;
    }
}

// layer-2 aggregate + pool + FC + finalize; 2 warps per node.
__global__ __launch_bounds__(256)
void aggregate2_pool_kernel(const __nv_bfloat16* __restrict__ yb,
                            const float* __restrict__ bias,
                            const float* __restrict__ wfc,
                            const int* __restrict__ batch, int n,
                            float* __restrict__ out, const float* __restrict__ bfc) {
    __shared__ float sbuf[4][32][9];
    __shared__ int is_last;
    int sub  = threadIdx.x >> 6;
    int half = (threadIdx.x >> 5) & 1;
    int lane = threadIdx.x & 31;
    int gw = blockIdx.x * 4 + sub;

    float acc[8] = {};
    int e0 = 0, e1 = 0;
    if (gw < n) { e0 = g_rowstart[gw]; e1 = g_rowstart[gw + 1]; }
    int mid = e0 + ((e1 - e0) >> 1);
    int lo = half ? mid : e0;
    int hi = half ? e1 : mid;
    gather_range<0>(acc, yb, lo, hi, lane);
    if (half && gw < n) {   // self loop on warp 1
        uint4 v = ((const uint4*)(yb + (size_t)gw * DH))[lane];
        acc8(acc, v, 1.f);
    }
    if (half) {
        #pragma unroll
        for (int q = 0; q < 8; ++q) sbuf[sub][lane][q] = acc[q];
    }
    __syncthreads();
    if (!half && gw < n) {
        #pragma unroll
        for (int q = 0; q < 8; ++q) acc[q] += sbuf[sub][lane][q];
        float dv = g_dinv[gw];
        float4 b0 = ((const float4*)bias)[2 * lane];
        float4 b1 = ((const float4*)bias)[2 * lane + 1];
        float4 f0 = ((const float4*)wfc)[2 * lane];
        float4 f1 = ((const float4*)wfc)[2 * lane + 1];

        float h;
        float dot = 0.f;
        h = fmaxf(dv * acc[0] + b0.x, 0.f); dot += h * f0.x;
        h = fmaxf(dv * acc[1] + b0.y, 0.f); dot += h * f0.y;
        h = fmaxf(dv * acc[2] + b0.z, 0.f); dot += h * f0.z;
        h = fmaxf(dv * acc[3] + b0.w, 0.f); dot += h * f0.w;
        h = fmaxf(dv * acc[4] + b1.x, 0.f); dot += h * f1.x;
        h = fmaxf(dv * acc[5] + b1.y, 0.f); dot += h * f1.y;
        h = fmaxf(dv * acc[6] + b1.z, 0.f); dot += h * f1.z;
        h = fmaxf(dv * acc[7] + b1.w, 0.f); dot += h * f1.w;

        #pragma unroll
        for (int off = 16; off > 0; off >>= 1)
            dot += __shfl_xor_sync(0xffffffffu, dot, off);
        if (lane == 0)
            atomicAdd(&g_gsum[batch[gw]], dot);
    }

    // finalize: last block to finish writes the output
    __syncthreads();
    if (threadIdx.x == 0) {
        __threadfence();
        int d = atomicAdd(&g_done, 1);
        is_last = (d == (int)gridDim.x - 1) ? 1 : 0;
    }
    __syncthreads();
    if (is_last) {
        __threadfence();
        int g = threadIdx.x;
        if (g < NGR)
            out[g] = g_gsum[g] / fmaxf((float)g_cnt[g], 1.0f) + bfc[0];
    }
}

// ---------------- launch ------------------------------------------------------
extern "C" void kernel_launch(void* const* d_in, const int* in_sizes, int n_in,
                              void* d_out, int out_size) {
    const float* x     = (const float*)d_in[0];
    const int*   ei    = (const int*)  d_in[1];
    const int*   batch = (const int*)  d_in[2];
    const float* W1    = (const float*)d_in[3];
    const float* b1    = (const float*)d_in[4];
    const float* W2    = (const float*)d_in[5];
    const float* b2    = (const float*)d_in[6];
    const float* wfc   = (const float*)d_in[7];
    const float* bfc   = (const float*)d_in[8];
    float* out = (float*)d_out;

    int n = in_sizes[0] / DIN;   // 20000
    int e = in_sizes[1] / 2;     // 320000

    __nv_bfloat16* ybptr = nullptr;
    __half* hptr = nullptr;
    cudaGetSymbolAddress((void**)&ybptr, g_yb);
    cudaGetSymbolAddress((void**)&hptr, g_h);

    int gblocks = ((n + BM - 1) / BM) * (DH / BN);   // 157 * 4 = 628
    int tn = (n + 3) / 4;                            // 5000 agg blocks (4 nodes each)

    prep_kernel<<<192, 256>>>(W1, W2);

    hybrid_kernel<<<NCSR + gblocks, 128>>>(x, ybptr, n, ei, batch, e);

    aggregate1_kernel<<<tn, 256>>>(ybptr, b1, hptr, n);

    gemm2_kernel<<<gblocks, 128>>>(ybptr, n);

    aggregate2_pool_kernel<<<tn, 256>>>(ybptr, b2, wfc, batch, n, out, bfc);
}

// round 16
// speedup vs baseline: 1.1091x; 1.1091x over previous
#include <cuda_runtime.h>
#include <cuda_bf16.h>
#include <cuda_fp16.h>
#include <cstdint>

// Problem constants (fixed by dataset)
#define NMAX   20000
#define EMAX   320000
#define DIN    512
#define DH     256
#define NGR    128
#define NCSR   128                     // CSR-builder blocks inside hybrid kernel
#define CSR_THREADS (NCSR * 128)

// ---------------- scratch (static device globals; no runtime alloc) ----------
__device__ int   g_deg[NMAX];
__device__ int   g_rowstart[NMAX + 1];
__device__ int   g_cursor[NMAX];
__device__ int   g_csr[EMAX];
__device__ float g_dinv[NMAX];
__device__ __align__(16) __nv_bfloat16 g_yb[(size_t)NMAX * DH];   // bf16 gemm out (gather src)
__device__ __align__(16) __half g_h[(size_t)NMAX * DH];           // layer-1 hidden (fp16)
__device__ __align__(16) uint32_t g_w1p[(DIN / 2) * DH];          // W1 packed half2 pairs
__device__ __align__(16) uint32_t g_w2p[(DH / 2) * DH];           // W2 packed half2 pairs
__device__ float g_gsum[NGR];
__device__ int   g_cnt[NGR];
__device__ int   g_blocksum[NCSR];
__device__ volatile unsigned g_bar[4];

// ---------------- helpers -----------------------------------------------------
__device__ __forceinline__ uint32_t packh2(float a, float b) {
    __half2 h = __float22half2_rn(make_float2(a, b));
    return *reinterpret_cast<uint32_t*>(&h);
}

__device__ __forceinline__ void cpa16(uint32_t dst_smem, const void* src, int srcsize) {
    asm volatile("cp.async.cg.shared.global [%0], [%1], 16, %2;\n"
                 :: "r"(dst_smem), "l"(src), "r"(srcsize));
}
#define CP_COMMIT() asm volatile("cp.async.commit_group;\n" ::: "memory")
#define CP_WAIT0()  asm volatile("cp.async.wait_group 0;\n" ::: "memory")

// ---------------- prep: reset counters + pack W1/W2 into fp16 pair layout -----
__global__ void prep_kernel(const float* __restrict__ W1, const float* __restrict__ W2) {
    int gid = blockIdx.x * blockDim.x + threadIdx.x;
    int nthr = gridDim.x * blockDim.x;
    if (gid < 4) g_bar[gid] = 0u;
    const int t1 = (DIN / 2) * DH;
    for (int i = gid; i < t1; i += nthr) {
        int kp = i / DH, n = i % DH;
        g_w1p[i] = packh2(W1[(2 * kp) * DH + n], W1[(2 * kp + 1) * DH + n]);
    }
    const int t2 = (DH / 2) * DH;
    for (int i = gid; i < t2; i += nthr) {
        int kp = i / DH, n = i % DH;
        g_w2p[i] = packh2(W2[(2 * kp) * DH + n], W2[(2 * kp + 1) * DH + n]);
    }
}

// ---------------- spin barrier among the NCSR builder blocks ------------------
__device__ __forceinline__ void csr_barrier(int id) {
    __syncthreads();
    if (threadIdx.x == 0) {
        __threadfence();
        atomicAdd((unsigned*)(g_bar + id), 1u);
        while (g_bar[id] < (unsigned)NCSR) __nanosleep(128);
        __threadfence();
    }
    __syncthreads();
}

// ---------------- CSR build (blocks [0,NCSR) of hybrid kernel; 128 threads) ---
__device__ void csr_build(const int* __restrict__ ei, const int* __restrict__ batch,
                          int n, int e) {
    int tid  = threadIdx.x;
    int gtid = blockIdx.x * 128 + tid;

    __shared__ int sm[4];
    __shared__ int s_carry;

    for (int i = gtid; i < n; i += CSR_THREADS) g_deg[i] = 0;
    if (gtid < NGR) { g_gsum[gtid] = 0.0f; g_cnt[gtid] = 0; }
    if (gtid == 0)  g_rowstart[n] = e;
    csr_barrier(0);

    for (int i = gtid; i < e; i += CSR_THREADS) atomicAdd(&g_deg[ei[e + i]], 1);
    for (int i = gtid; i < n; i += CSR_THREADS) atomicAdd(&g_cnt[batch[i]], 1);
    csr_barrier(1);

    const int chunk = (n + NCSR - 1) / NCSR;
    int base = blockIdx.x * chunk;
    int lim  = n - base; if (lim > chunk) lim = chunk; if (lim < 0) lim = 0;

    int lane = tid & 31, wid = tid >> 5;

    int psum = 0;
    for (int i = tid; i < lim; i += 128) psum += __ldcg(&g_deg[base + i]);
    #pragma unroll
    for (int off = 16; off; off >>= 1) psum += __shfl_xor_sync(0xffffffffu, psum, off);
    if (lane == 0) sm[wid] = psum;
    __syncthreads();
    if (tid == 0) g_blocksum[blockIdx.x] = sm[0] + sm[1] + sm[2] + sm[3];
    csr_barrier(2);

    {
        int val = (tid < blockIdx.x) ? __ldcg(&g_blocksum[tid]) : 0;
        #pragma unroll
        for (int off = 16; off; off >>= 1) val += __shfl_xor_sync(0xffffffffu, val, off);
        if (lane == 0) sm[wid] = val;
        __syncthreads();
        if (tid == 0) s_carry = sm[0] + sm[1] + sm[2] + sm[3];
        __syncthreads();
    }
    int run = s_carry;
    __syncthreads();

    for (int o = 0; o < lim; o += 128) {
        int i = base + o + tid;
        int v = (o + tid < lim) ? __ldcg(&g_deg[i]) : 0;
        int x = v;
        #pragma unroll
        for (int off = 1; off < 32; off <<= 1) {
            int t = __shfl_up_sync(0xffffffffu, x, off);
            if (lane >= off) x += t;
        }
        if (lane == 31) sm[wid] = x;
        __syncthreads();
        if (wid == 0 && lane < 4) {
            int s = sm[lane];
            #pragma unroll
            for (int off = 1; off < 4; off <<= 1) {
                int t = __shfl_up_sync(0xfu, s, off);
                if (lane >= off) s += t;
            }
            sm[lane] = s;
        }
        __syncthreads();
        int woff = wid ? sm[wid - 1] : 0;
        if (o + tid < lim) {
            int excl = run + x + woff - v;
            g_rowstart[i] = excl;
            g_cursor[i]   = excl;
            g_dinv[i]     = rsqrtf((float)(v + 1));
        }
        run += sm[3];
        __syncthreads();
    }
    csr_barrier(3);

    for (int i = gtid; i < e; i += CSR_THREADS) {
        int s = ei[i];
        int d = ei[e + i];
        int p = atomicAdd(&g_cursor[d], 1);
        g_csr[p] = s;
    }
}

// ---------------- fp16 tensor-core GEMM (m16n8k16, fp32 accum) ----------------
__device__ __forceinline__ void mma_f16(float* c, const uint32_t* a, const uint32_t* b) {
    asm volatile(
        "mma.sync.aligned.m16n8k16.row.col.f32.f16.f16.f32 "
        "{%0,%1,%2,%3}, {%4,%5,%6,%7}, {%8,%9}, {%0,%1,%2,%3};\n"
        : "+f"(c[0]), "+f"(c[1]), "+f"(c[2]), "+f"(c[3])
        : "r"(a[0]), "r"(a[1]), "r"(a[2]), "r"(a[3]),
          "r"(b[0]), "r"(b[1]));
}

#define BN 64
#define KPT 16      // k-pairs per tile (= 32 k-values)
#define ASPAD 20
#define BSPAD 72

// BMT: M tile (64 or 128). Each of 4 warps covers BMT/2 rows x 32 cols.
// AF16=1: A is fp16 k-pair u32 rows, loaded via cp.async (zero-fill OOB).
// AF16=0: A is fp32, reg-staged + packed (only instantiated with BMT=128).
template <int AF16, int BMT>
__device__ __forceinline__ void gemm_core(
    const float* __restrict__ Af, const uint32_t* __restrict__ Ah,
    const uint32_t* __restrict__ Bp,
    const float* __restrict__ scale, __nv_bfloat16* __restrict__ Yb,
    int M, int K, int bid,
    uint32_t (*As)[ASPAD], uint32_t (*Bs)[BSPAD]) {

    const int MI = BMT / 32;                  // m16 frags per warp
    int tid  = threadIdx.x;
    int lane = tid & 31, warp = tid >> 5;
    int wm = warp >> 1, wn = warp & 1;
    int gid = lane >> 2, tig = lane & 3;
    int m0 = (bid >> 2) * BMT;
    int n0 = (bid & 3) * BN;
    const int KPr = K >> 1;

    uint32_t as_base = (uint32_t)__cvta_generic_to_shared(&As[0][0]);
    uint32_t bs_base = (uint32_t)__cvta_generic_to_shared(&Bs[0][0]);

    float c[MI][4][4] = {};
    float4 pa[8];

    auto loadB = [&](int kt, int s) {
        const uint32_t* src = Bp + (size_t)(kt * KPT) * DH + n0;
        #pragma unroll
        for (int t = 0; t < 2; ++t) {
            int cidx = tid + t * 128;
            int kp = cidx >> 4, cc = (cidx & 15) << 2;
            cpa16(bs_base + (((s * KPT + kp) * BSPAD) + cc) * 4, src + kp * DH + cc, 16);
        }
    };
    auto loadA16 = [&](int kt, int s) {
        #pragma unroll
        for (int t = 0; t < BMT / 32; ++t) {
            int cidx = tid + t * 128;
            int r = cidx >> 2, cc = (cidx & 3) << 2;
            int gr = m0 + r;
            int sz = (gr < M) ? 16 : 0;
            const uint32_t* src = Ah + (size_t)(gr < M ? gr : 0) * KPr + kt * KPT + cc;
            cpa16(as_base + (((s * BMT + r) * ASPAD) + cc) * 4, src, sz);
        }
    };
    auto ldAreg = [&](int kt) {
        #pragma unroll
        for (int t = 0; t < 8; ++t) {
            int f4 = tid + t * 128;
            int r = f4 >> 3, cc = (f4 & 7) << 2;
            int gr = m0 + r;
            pa[t] = (gr < M) ? *(const float4*)(Af + (size_t)gr * K + kt * 32 + cc)
                             : make_float4(0.f, 0.f, 0.f, 0.f);
        }
    };
    auto stA = [&](int s) {
        #pragma unroll
        for (int t = 0; t < 8; ++t) {
            int f4 = tid + t * 128;
            int r = f4 >> 3, cc = (f4 & 7) << 2;
            uint2 v = make_uint2(packh2(pa[t].x, pa[t].y), packh2(pa[t].z, pa[t].w));
            *(uint2*)&As[s * BMT + r][cc >> 1] = v;
        }
    };
    auto compute = [&](int s) {
        #pragma unroll
        for (int ks = 0; ks < 2; ++ks) {
            int kk2 = ks * 8;
            uint32_t a[MI][4], b[4][2];
            #pragma unroll
            for (int i = 0; i < MI; ++i) {
                int mrow = s * BMT + wm * (BMT / 2) + i * 16;
                a[i][0] = As[mrow + gid][kk2 + tig];
                a[i][1] = As[mrow + gid + 8][kk2 + tig];
                a[i][2] = As[mrow + gid][kk2 + tig + 4];
                a[i][3] = As[mrow + gid + 8][kk2 + tig + 4];
            }
            #pragma unroll
            for (int j = 0; j < 4; ++j) {
                int ncol = wn * 32 + j * 8 + gid;
                b[j][0] = Bs[s * KPT + kk2 + tig][ncol];
                b[j][1] = Bs[s * KPT + kk2 + tig + 4][ncol];
            }
            #pragma unroll
            for (int i = 0; i < MI; ++i)
                #pragma unroll
                for (int j = 0; j < 4; ++j)
                    mma_f16(c[i][j], a[i], b[j]);
        }
    };

    int KT = K / 32;
    loadB(0, 0);
    if (AF16) loadA16(0, 0); else ldAreg(0);
    CP_COMMIT();
    if (!AF16) stA(0);
    CP_WAIT0();
    __syncthreads();

    for (int kt = 0; kt < KT; ++kt) {
        int s = kt & 1;
        if (kt + 1 < KT) {
            loadB(kt + 1, s ^ 1);
            if (AF16) loadA16(kt + 1, s ^ 1); else ldAreg(kt + 1);
            CP_COMMIT();
        }
        compute(s);
        if (!AF16 && kt + 1 < KT) stA(s ^ 1);
        if (kt + 1 < KT) { CP_WAIT0(); __syncthreads(); }
    }

    #pragma unroll
    for (int i = 0; i < MI; ++i) {
        int r0 = m0 + wm * (BMT / 2) + i * 16 + gid;
        int r1 = r0 + 8;
        float s0 = 1.f, s1 = 1.f;
        if (scale) {
            s0 = (r0 < M) ? scale[r0] : 0.f;
            s1 = (r1 < M) ? scale[r1] : 0.f;
        }
        #pragma unroll
        for (int j = 0; j < 4; ++j) {
            int cb = n0 + wn * 32 + j * 8 + tig * 2;
            if (r0 < M) {
                __nv_bfloat162 v = __float22bfloat162_rn(
                    make_float2(s0 * c[i][j][0], s0 * c[i][j][1]));
                *(__nv_bfloat162*)(Yb + (size_t)r0 * DH + cb) = v;
            }
            if (r1 < M) {
                __nv_bfloat162 v = __float22bfloat162_rn(
                    make_float2(s1 * c[i][j][2], s1 * c[i][j][3]));
                *(__nv_bfloat162*)(Yb + (size_t)r1 * DH + cb) = v;
            }
        }
    }
}

// hybrid: blocks [0,NCSR) build CSR; the rest compute Yb = bf16(X @ W1) (unscaled)
__global__ __launch_bounds__(128, 2)
void hybrid_kernel(const float* __restrict__ x,
                   __nv_bfloat16* __restrict__ yb, int n,
                   const int* __restrict__ ei, const int* __restrict__ batch, int e) {
    __shared__ __align__(16) uint32_t As[2 * 128][ASPAD];
    __shared__ __align__(16) uint32_t Bs[2 * KPT][BSPAD];
    if (blockIdx.x < NCSR) { csr_build(ei, batch, n, e); return; }
    gemm_core<0, 128>(x, nullptr, g_w1p, nullptr, yb, n, DIN, blockIdx.x - NCSR, As, Bs);
}

// gemm2: yb = bf16( dinv[m] * (h @ W2) ); BMT=64 for wave balance (1252 blocks)
__global__ __launch_bounds__(128, 4)
void gemm2_kernel(__nv_bfloat16* __restrict__ Yb, int M) {
    __shared__ __align__(16) uint32_t As[2 * 64][ASPAD];
    __shared__ __align__(16) uint32_t Bs[2 * KPT][BSPAD];
    gemm_core<1, 64>(nullptr, (const uint32_t*)g_h, g_w2p, g_dinv, Yb, M, DH,
                     blockIdx.x, As, Bs);
}

// ---------------- gather helper ------------------------------------------------
__device__ __forceinline__ void acc8(float* acc, uint4 v, float dv) {
    const __nv_bfloat162* b = reinterpret_cast<const __nv_bfloat162*>(&v);
    #pragma unroll
    for (int q = 0; q < 4; ++q) {
        float2 f = __bfloat1622float2(b[q]);
        acc[2 * q]     = fmaf(dv, f.x, acc[2 * q]);
        acc[2 * q + 1] = fmaf(dv, f.y, acc[2 * q + 1]);
    }
}

// layer 1: yb holds UNscaled bf16(X@W1); apply dinv[src]; output fp16 h.
__global__ __launch_bounds__(256)
void aggregate1_kernel(const __nv_bfloat16* __restrict__ yb,
                       const float* __restrict__ bias,
                       __half* __restrict__ out, int n) {
    int gw   = (blockIdx.x * blockDim.x + threadIdx.x) >> 5;
    int lane = threadIdx.x & 31;
    if (gw >= n) return;
    int e0 = g_rowstart[gw], e1 = g_rowstart[gw + 1];

    float acc[8] = {};
    int e = e0;
    for (; e + 4 <= e1; e += 4) {
        int s0 = g_csr[e], s1 = g_csr[e + 1], s2 = g_csr[e + 2], s3 = g_csr[e + 3];
        float d0 = g_dinv[s0], d1 = g_dinv[s1], d2 = g_dinv[s2], d3 = g_dinv[s3];
        uint4 v0 = ((const uint4*)(yb + (size_t)s0 * DH))[lane];
        uint4 v1 = ((const uint4*)(yb + (size_t)s1 * DH))[lane];
        uint4 v2 = ((const uint4*)(yb + (size_t)s2 * DH))[lane];
        uint4 v3 = ((const uint4*)(yb + (size_t)s3 * DH))[lane];
        acc8(acc, v0, d0); acc8(acc, v1, d1); acc8(acc, v2, d2); acc8(acc, v3, d3);
    }
    for (; e < e1; ++e) {
        int s = g_csr[e];
        uint4 v = ((const uint4*)(yb + (size_t)s * DH))[lane];
        acc8(acc, v, g_dinv[s]);
    }
    float dvn = g_dinv[gw];
    {
        uint4 v = ((const uint4*)(yb + (size_t)gw * DH))[lane];
        acc8(acc, v, dvn);
    }
    float4 b0 = ((const float4*)bias)[2 * lane];
    float4 b1 = ((const float4*)bias)[2 * lane + 1];
    float r[8];
    r[0] = fmaxf(dvn * acc[0] + b0.x, 0.f); r[1] = fmaxf(dvn * acc[1] + b0.y, 0.f);
    r[2] = fmaxf(dvn * acc[2] + b0.z, 0.f); r[3] = fmaxf(dvn * acc[3] + b0.w, 0.f);
    r[4] = fmaxf(dvn * acc[4] + b1.x, 0.f); r[5] = fmaxf(dvn * acc[5] + b1.y, 0.f);
    r[6] = fmaxf(dvn * acc[6] + b1.z, 0.f); r[7] = fmaxf(dvn * acc[7] + b1.w, 0.f);
    uint4 st;
    uint32_t* sp = reinterpret_cast<uint32_t*>(&st);
    sp[0] = packh2(r[0], r[1]); sp[1] = packh2(r[2], r[3]);
    sp[2] = packh2(r[4], r[5]); sp[3] = packh2(r[6], r[7]);
    ((uint4*)(out + (size_t)gw * DH))[lane] = st;
}

// layer-2 aggregate fused with pool+FC (yb pre-scaled by dinv[src] in gemm2)
__global__ __launch_bounds__(256)
void aggregate2_pool_kernel(const __nv_bfloat16* __restrict__ yb,
                            const float* __restrict__ bias,
                            const float* __restrict__ wfc,
                            const int* __restrict__ batch, int n) {
    int gw   = (blockIdx.x * blockDim.x + threadIdx.x) >> 5;
    int lane = threadIdx.x & 31;
    if (gw >= n) return;
    int e0 = g_rowstart[gw], e1 = g_rowstart[gw + 1];

    float acc[8] = {};
    int e = e0;
    for (; e + 4 <= e1; e += 4) {
        int s0 = g_csr[e], s1 = g_csr[e + 1], s2 = g_csr[e + 2], s3 = g_csr[e + 3];
        uint4 v0 = ((const uint4*)(yb + (size_t)s0 * DH))[lane];
        uint4 v1 = ((const uint4*)(yb + (size_t)s1 * DH))[lane];
        uint4 v2 = ((const uint4*)(yb + (size_t)s2 * DH))[lane];
        uint4 v3 = ((const uint4*)(yb + (size_t)s3 * DH))[lane];
        acc8(acc, v0, 1.f); acc8(acc, v1, 1.f); acc8(acc, v2, 1.f); acc8(acc, v3, 1.f);
    }
    for (; e < e1; ++e) {
        int s = g_csr[e];
        uint4 v = ((const uint4*)(yb + (size_t)s * DH))[lane];
        acc8(acc, v, 1.f);
    }
    {
        uint4 v = ((const uint4*)(yb + (size_t)gw * DH))[lane];
        acc8(acc, v, 1.f);
    }
    float dv = g_dinv[gw];
    float4 b0 = ((const float4*)bias)[2 * lane];
    float4 b1 = ((const float4*)bias)[2 * lane + 1];
    float4 f0 = ((const float4*)wfc)[2 * lane];
    float4 f1 = ((const float4*)wfc)[2 * lane + 1];

    float h;
    float dot = 0.f;
    h = fmaxf(dv * acc[0] + b0.x, 0.f); dot += h * f0.x;
    h = fmaxf(dv * acc[1] + b0.y, 0.f); dot += h * f0.y;
    h = fmaxf(dv * acc[2] + b0.z, 0.f); dot += h * f0.z;
    h = fmaxf(dv * acc[3] + b0.w, 0.f); dot += h * f0.w;
    h = fmaxf(dv * acc[4] + b1.x, 0.f); dot += h * f1.x;
    h = fmaxf(dv * acc[5] + b1.y, 0.f); dot += h * f1.y;
    h = fmaxf(dv * acc[6] + b1.z, 0.f); dot += h * f1.z;
    h = fmaxf(dv * acc[7] + b1.w, 0.f); dot += h * f1.w;

    #pragma unroll
    for (int off = 16; off > 0; off >>= 1)
        dot += __shfl_xor_sync(0xffffffffu, dot, off);
    if (lane == 0)
        atomicAdd(&g_gsum[batch[gw]], dot);
}

__global__ void finalize_kernel(float* __restrict__ out, const float* __restrict__ bfc) {
    int g = threadIdx.x;
    if (g < NGR)
        out[g] = g_gsum[g] / fmaxf((float)g_cnt[g], 1.0f) + bfc[0];
}

// ---------------- launch ------------------------------------------------------
extern "C" void kernel_launch(void* const* d_in, const int* in_sizes, int n_in,
                              void* d_out, int out_size) {
    const float* x     = (const float*)d_in[0];
    const int*   ei    = (const int*)  d_in[1];
    const int*   batch = (const int*)  d_in[2];
    const float* W1    = (const float*)d_in[3];
    const float* b1    = (const float*)d_in[4];
    const float* W2    = (const float*)d_in[5];
    const float* b2    = (const float*)d_in[6];
    const float* wfc   = (const float*)d_in[7];
    const float* bfc   = (const float*)d_in[8];
    float* out = (float*)d_out;

    int n = in_sizes[0] / DIN;   // 20000
    int e = in_sizes[1] / 2;     // 320000

    __nv_bfloat16* ybptr = nullptr;
    __half* hptr = nullptr;
    cudaGetSymbolAddress((void**)&ybptr, g_yb);
    cudaGetSymbolAddress((void**)&hptr, g_h);

    int g1blocks = ((n + 127) / 128) * (DH / BN);    // 157 * 4 = 628
    int g2blocks = ((n + 63) / 64) * (DH / BN);      // 313 * 4 = 1252
    int ta = ((n * 32) + 255) / 256;                 // 2500

    prep_kernel<<<192, 256>>>(W1, W2);

    hybrid_kernel<<<NCSR + g1blocks, 128>>>(x, ybptr, n, ei, batch, e);

    aggregate1_kernel<<<ta, 256>>>(ybptr, b1, hptr, n);

    gemm2_kernel<<<g2blocks, 128>>>(ybptr, n);

    aggregate2_pool_kernel<<<ta, 256>>>(ybptr, b2, wfc, batch, n);

    finalize_kernel<<<1, NGR>>>(out, bfc);
}